// round 5
// baseline (speedup 1.0000x reference)
#include <cuda_runtime.h>
#include <cuda_bf16.h>
#include <cstdint>

// Detector post-process: persistent blocks, depth-4 cp.async ring staging
// scores+box+conf, 4-threads-per-box argmax via packed shuffle reduction.
//
// Output (flat float32): [box_out (B*4) | probs (B) | class_index (B)]

#ifndef THRESHOLD
#define THRESHOLD 0.5f
#endif

#define TB 128               // threads per block
#define BOXES 32             // boxes per tile
#define SLOTS 20             // float4 per box (80 classes)
#define PAD 21               // padded f4 stride per box in smem
#define SC_F4 (BOXES * PAD)  // 672  scores region (f4)
#define BX_OFF SC_F4         // 672  box region (32 f4)
#define CF_OFF (SC_F4 + 32)  // 704  conf region (8 f4)
#define STAGE_F4 712         // total f4 per stage
#define DEPTH 4

__device__ __forceinline__ void cp_async16(uint32_t saddr, const void* gptr) {
    asm volatile("cp.async.cg.shared.global [%0], [%1], 16;\n"
                 :: "r"(saddr), "l"(gptr) : "memory");
}
__device__ __forceinline__ void cp_commit() {
    asm volatile("cp.async.commit_group;\n" ::: "memory");
}
__device__ __forceinline__ void cp_wait3() {
    asm volatile("cp.async.wait_group 3;\n" ::: "memory");
}

__global__ __launch_bounds__(TB) void detector_kernel(
    const float4* __restrict__ box,
    const float*  __restrict__ conf,
    const float4* __restrict__ score4,     // [B*20]
    const float4* __restrict__ prior,
    const unsigned* __restrict__ feat_raw,
    float4* __restrict__ box_out,
    float*  __restrict__ probs_out,
    float*  __restrict__ cls_out,
    int n_boxes, int prior_mod, int n_tiles)
{
    __shared__ float4 sbuf[DEPTH][STAGE_F4];   // 4 x 11392 B = 45568 B

    const int t = threadIdx.x;

    // feat_size may arrive as int32 or float32 bits; decode robustly.
    unsigned fb = *feat_raw;
    float feat = (fb < 0x01000000u) ? (float)fb : __uint_as_float(fb);
    float inv_feat = 1.0f / feat;

    const long long total_sc_f4 = (long long)n_boxes * SLOTS;
    const int conf_f4 = (n_boxes + 3) / 4;

    auto prefetch = [&](int tile, int st) {
        if (tile < n_tiles) {
            const int box0 = tile * BOXES;
            const long long sbase_g = (long long)box0 * SLOTS;
            uint32_t sb = (uint32_t)__cvta_generic_to_shared(&sbuf[st][0]);
            // scores: 640 f4, thread t copies r*TB+t
            #pragma unroll
            for (int r = 0; r < (BOXES * SLOTS) / TB; r++) {
                int g = r * TB + t;
                if (sbase_g + g < total_sc_f4) {
                    int b = g / SLOTS;
                    int s = g - b * SLOTS;
                    cp_async16(sb + (uint32_t)(b * PAD + s) * 16u,
                               score4 + sbase_g + g);
                }
            }
            // box: 32 f4 (threads 0-31), conf: 8 f4 (threads 32-39)
            if (t < BOXES) {
                if (box0 + t < n_boxes)
                    cp_async16(sb + (uint32_t)(BX_OFF + t) * 16u,
                               box + box0 + t);
            } else if (t < BOXES + 8) {
                int l = t - BOXES;
                int g = box0 / 4 + l;       // box0 multiple of 32 -> aligned
                if (g < conf_f4)
                    cp_async16(sb + (uint32_t)(CF_OFF + l) * 16u,
                               (const float4*)conf + g);
            }
        }
        cp_commit();   // uniform group accounting even past the end
    };

    int tile = blockIdx.x;
    const int stride = gridDim.x;

    prefetch(tile, 0);
    prefetch(tile + stride, 1);
    prefetch(tile + 2 * stride, 2);

    int bf = 0;
    for (; tile < n_tiles; tile += stride, bf = (bf + 1) & 3) {
        prefetch(tile + 3 * stride, (bf + 3) & 3);
        cp_wait3();            // oldest group (this tile) complete
        __syncthreads();       // cross-thread smem visibility

        // ---- compute: 4 threads per box, 5 slots each ----
        const int bx = t >> 2;            // box within tile
        const int q  = t & 3;             // quarter
        const int i  = tile * BOXES + bx;
        if (i < n_boxes) {
            const float4* s = &sbuf[bf][bx * PAD + q * 5];
            const float c = ((const float*)&sbuf[bf][CF_OFF])[bx];
            float best = -3.402823466e+38f;
            int bidx = 0;
            #pragma unroll
            for (int j = 0; j < 5; j++) {
                float4 v = s[j];
                float p0 = c * v.x, p1 = c * v.y, p2 = c * v.z, p3 = c * v.w;
                int base = (q * 5 + j) * 4;
                if (p0 > best) { best = p0; bidx = base;     }
                if (p1 > best) { best = p1; bidx = base + 1; }
                if (p2 > best) { best = p2; bidx = base + 2; }
                if (p3 > best) { best = p3; bidx = base + 3; }
            }
            // pack and reduce across the 4 quarters (width-4 bfly)
            unsigned long long pk =
                ((unsigned long long)__float_as_uint(best) << 32) |
                (unsigned)(127 - bidx);
            unsigned long long o1 = __shfl_xor_sync(0xFFFFFFFFu, pk, 1, 4);
            if (o1 > pk) pk = o1;
            unsigned long long o2 = __shfl_xor_sync(0xFFFFFFFFu, pk, 2, 4);
            if (o2 > pk) pk = o2;

            if (q == 0) {
                float prob = __uint_as_float((unsigned)(pk >> 32));
                int cls = 127 - (int)(pk & 0xFFu);

                float4 b4 = sbuf[bf][BX_OFF + bx];
                float4 p  = prior[i % prior_mod];
                float cx = b4.x + p.x;
                float cy = b4.y + p.y;
                float hw = 0.5f * (b4.z * p.z);
                float hh = 0.5f * (b4.w * p.w);

                float4 corners;
                corners.x = (cx - hw) * inv_feat;
                corners.y = (cy - hh) * inv_feat;
                corners.z = (cx + hw) * inv_feat;
                corners.w = (cy + hh) * inv_feat;

                bool m = prob > THRESHOLD;
                box_out[i]   = m ? corners : make_float4(0.f, 0.f, 0.f, 0.f);
                probs_out[i] = m ? prob : 0.0f;
                cls_out[i]   = (float)cls;
            }
        }
        __syncthreads();   // buffer free before it is re-targeted
    }
}

extern "C" void kernel_launch(void* const* d_in, const int* in_sizes, int n_in,
                              void* d_out, int out_size)
{
    const float4*   box    = (const float4*)d_in[0];
    const float*    conf   = (const float*)d_in[1];
    const float4*   score4 = (const float4*)d_in[2];
    const float4*   prior  = (const float4*)d_in[3];
    const unsigned* feat   = (const unsigned*)d_in[4];

    int n_boxes   = in_sizes[1];       // N*HW*A
    int prior_mod = in_sizes[3] / 4;   // HW*A
    int n_tiles   = (n_boxes + BOXES - 1) / BOXES;

    float* out       = (float*)d_out;
    float4* box_out  = (float4*)out;
    float*  probs    = out + (size_t)n_boxes * 4;
    float*  cls      = out + (size_t)n_boxes * 5;

    int blocks = 148 * 5;              // persistent, 5 blocks/SM (45.5 KB smem)
    if (blocks > n_tiles) blocks = n_tiles;

    detector_kernel<<<blocks, TB>>>(box, conf, score4, prior, feat,
                                    box_out, probs, cls,
                                    n_boxes, prior_mod, n_tiles);
}

// round 6
// speedup vs baseline: 1.1030x; 1.1030x over previous
#include <cuda_runtime.h>
#include <cuda_bf16.h>
#include <cstdint>

// Detector post-process: persistent blocks, depth-4 TMA-bulk (cp.async.bulk)
// ring staging scores+box+conf, 4-threads-per-box packed-shuffle argmax.
//
// Output (flat float32): [box_out (B*4) | probs (B) | class_index (B)]

#ifndef THRESHOLD
#define THRESHOLD 0.5f
#endif

#define TB 128                    // threads per block
#define BOXES 32                  // boxes per tile
#define SC_BYTES (BOXES * 320)    // 10240 contiguous score bytes per tile
#define BX_OFF SC_BYTES           // box region offset (512 B)
#define CF_OFF (SC_BYTES + 512)   // conf region offset (128 B)
#define STAGE_BYTES (SC_BYTES + 512 + 128)   // 10880
#define DEPTH 4

__device__ __forceinline__ uint32_t s2u32(const void* p) {
    return (uint32_t)__cvta_generic_to_shared(p);
}
__device__ __forceinline__ void mbar_init(uint32_t mb, uint32_t cnt) {
    asm volatile("mbarrier.init.shared.b64 [%0], %1;" :: "r"(mb), "r"(cnt) : "memory");
}
__device__ __forceinline__ void mbar_expect_tx(uint32_t mb, uint32_t bytes) {
    asm volatile("mbarrier.arrive.expect_tx.shared.b64 _, [%0], %1;"
                 :: "r"(mb), "r"(bytes) : "memory");
}
__device__ __forceinline__ void bulk_g2s(uint32_t sdst, const void* gsrc,
                                         uint32_t bytes, uint32_t mb) {
    asm volatile(
        "cp.async.bulk.shared::cta.global.mbarrier::complete_tx::bytes "
        "[%0], [%1], %2, [%3];"
        :: "r"(sdst), "l"(gsrc), "r"(bytes), "r"(mb) : "memory");
}
__device__ __forceinline__ void mbar_wait(uint32_t mb, uint32_t ph) {
    asm volatile(
        "{\n\t.reg .pred P;\n\t"
        "W%=:\n\t"
        "mbarrier.try_wait.parity.acquire.cta.shared::cta.b64 P, [%0], %1;\n\t"
        "@!P bra W%=;\n\t"
        "}"
        :: "r"(mb), "r"(ph) : "memory");
}

__global__ __launch_bounds__(TB) void detector_kernel(
    const float4* __restrict__ box,
    const float*  __restrict__ conf,
    const float4* __restrict__ score4,     // [B*20]
    const float4* __restrict__ prior,
    const unsigned* __restrict__ feat_raw,
    float4* __restrict__ box_out,
    float*  __restrict__ probs_out,
    float*  __restrict__ cls_out,
    int n_boxes, int prior_mod, int n_full_tiles)
{
    __shared__ __align__(128) char ring[DEPTH][STAGE_BYTES];  // 43520 B
    __shared__ unsigned long long mbar[DEPTH];

    const int t = threadIdx.x;

    if (t == 0) {
        #pragma unroll
        for (int d = 0; d < DEPTH; d++) mbar_init(s2u32(&mbar[d]), 1);
        // fence init -> async proxy
        asm volatile("fence.proxy.async.shared::cta;" ::: "memory");
    }
    __syncthreads();

    // feat_size may arrive as int32 or float32 bits; decode robustly.
    unsigned fb = *feat_raw;
    float feat = (fb < 0x01000000u) ? (float)fb : __uint_as_float(fb);
    float inv_feat = 1.0f / feat;

    auto prefetch = [&](int tile, int st) {
        if (t == 0 && tile < n_full_tiles) {
            uint32_t sb = s2u32(&ring[st][0]);
            uint32_t mb = s2u32(&mbar[st]);
            const char* sc_src = (const char*)score4 + (size_t)tile * SC_BYTES;
            mbar_expect_tx(mb, STAGE_BYTES);
            bulk_g2s(sb,          sc_src,                 SC_BYTES, mb);
            bulk_g2s(sb + BX_OFF, box  + tile * BOXES,    512,      mb);
            bulk_g2s(sb + CF_OFF, conf + tile * BOXES,    128,      mb);
        }
    };

    int tile = blockIdx.x;
    const int stride = gridDim.x;

    prefetch(tile, 0);
    prefetch(tile + stride, 1);
    prefetch(tile + 2 * stride, 2);

    int bf = 0, ph = 0;
    const int bx = t >> 2;     // box within tile
    const int q  = t & 3;      // quarter of the 80 classes

    for (; tile < n_full_tiles; tile += stride) {
        prefetch(tile + 3 * stride, (bf + 3) & 3);
        mbar_wait(s2u32(&mbar[bf]), ph);

        // ---- compute: 4 threads per box, 5 float4 slots each ----
        const int i = tile * BOXES + bx;
        {
            const float4* s = (const float4*)&ring[bf][0] + bx * 20 + q * 5;
            const float c = ((const float*)&ring[bf][CF_OFF])[bx];
            float best = -3.402823466e+38f;
            int bidx = 0;
            #pragma unroll
            for (int j = 0; j < 5; j++) {
                float4 v = s[j];
                float p0 = c * v.x, p1 = c * v.y, p2 = c * v.z, p3 = c * v.w;
                int base = (q * 5 + j) * 4;
                if (p0 > best) { best = p0; bidx = base;     }
                if (p1 > best) { best = p1; bidx = base + 1; }
                if (p2 > best) { best = p2; bidx = base + 2; }
                if (p3 > best) { best = p3; bidx = base + 3; }
            }
            // pack: non-negative fp32 bits monotonic; low byte favors smaller
            // class on exact ties (matches jnp.argmax first occurrence).
            unsigned long long pk =
                ((unsigned long long)__float_as_uint(best) << 32) |
                (unsigned)(127 - bidx);
            unsigned long long o1 = __shfl_xor_sync(0xFFFFFFFFu, pk, 1, 4);
            if (o1 > pk) pk = o1;
            unsigned long long o2 = __shfl_xor_sync(0xFFFFFFFFu, pk, 2, 4);
            if (o2 > pk) pk = o2;

            if (q == 0) {
                float prob = __uint_as_float((unsigned)(pk >> 32));
                int cls = 127 - (int)(pk & 0xFFu);

                float4 b4 = ((const float4*)&ring[bf][BX_OFF])[bx];
                float4 p  = prior[i % prior_mod];
                float cx = b4.x + p.x;
                float cy = b4.y + p.y;
                float hw = 0.5f * (b4.z * p.z);
                float hh = 0.5f * (b4.w * p.w);

                float4 corners;
                corners.x = (cx - hw) * inv_feat;
                corners.y = (cy - hh) * inv_feat;
                corners.z = (cx + hw) * inv_feat;
                corners.w = (cy + hh) * inv_feat;

                bool m = prob > THRESHOLD;
                box_out[i]   = m ? corners : make_float4(0.f, 0.f, 0.f, 0.f);
                probs_out[i] = m ? prob : 0.0f;
                cls_out[i]   = (float)cls;
            }
        }
        __syncthreads();   // all reads done before stage is re-armed
        bf = (bf + 1) & 3;
        if (bf == 0) ph ^= 1;
    }

    // ---- tail boxes (n_boxes not multiple of BOXES): direct GMEM path ----
    int tail0 = n_full_tiles * BOXES;
    if (blockIdx.x == 0 && tail0 < n_boxes) {
        int i = tail0 + bx;
        if (bx < BOXES && i < n_boxes) {
            float c = conf[i];
            const float4* s = score4 + (size_t)i * 20 + q * 5;
            float best = -3.402823466e+38f;
            int bidx = 0;
            #pragma unroll
            for (int j = 0; j < 5; j++) {
                float4 v = s[j];
                float p0 = c * v.x, p1 = c * v.y, p2 = c * v.z, p3 = c * v.w;
                int base = (q * 5 + j) * 4;
                if (p0 > best) { best = p0; bidx = base;     }
                if (p1 > best) { best = p1; bidx = base + 1; }
                if (p2 > best) { best = p2; bidx = base + 2; }
                if (p3 > best) { best = p3; bidx = base + 3; }
            }
            unsigned long long pk =
                ((unsigned long long)__float_as_uint(best) << 32) |
                (unsigned)(127 - bidx);
            unsigned long long o1 = __shfl_xor_sync(0xFFFFFFFFu, pk, 1, 4);
            if (o1 > pk) pk = o1;
            unsigned long long o2 = __shfl_xor_sync(0xFFFFFFFFu, pk, 2, 4);
            if (o2 > pk) pk = o2;
            if (q == 0) {
                float prob = __uint_as_float((unsigned)(pk >> 32));
                int cls = 127 - (int)(pk & 0xFFu);
                float4 b4 = box[i];
                float4 p  = prior[i % prior_mod];
                float cx = b4.x + p.x, cy = b4.y + p.y;
                float hw = 0.5f * (b4.z * p.z), hh = 0.5f * (b4.w * p.w);
                float4 corners;
                corners.x = (cx - hw) * inv_feat;
                corners.y = (cy - hh) * inv_feat;
                corners.z = (cx + hw) * inv_feat;
                corners.w = (cy + hh) * inv_feat;
                bool m = prob > THRESHOLD;
                box_out[i]   = m ? corners : make_float4(0.f, 0.f, 0.f, 0.f);
                probs_out[i] = m ? prob : 0.0f;
                cls_out[i]   = (float)cls;
            }
        }
    }
}

extern "C" void kernel_launch(void* const* d_in, const int* in_sizes, int n_in,
                              void* d_out, int out_size)
{
    const float4*   box    = (const float4*)d_in[0];
    const float*    conf   = (const float*)d_in[1];
    const float4*   score4 = (const float4*)d_in[2];
    const float4*   prior  = (const float4*)d_in[3];
    const unsigned* feat   = (const unsigned*)d_in[4];

    int n_boxes      = in_sizes[1];       // N*HW*A
    int prior_mod    = in_sizes[3] / 4;   // HW*A
    int n_full_tiles = n_boxes / BOXES;

    float* out       = (float*)d_out;
    float4* box_out  = (float4*)out;
    float*  probs    = out + (size_t)n_boxes * 4;
    float*  cls      = out + (size_t)n_boxes * 5;

    int blocks = 148 * 5;                 // persistent, 5 blocks/SM (43.6 KB)
    if (blocks > n_full_tiles) blocks = n_full_tiles > 0 ? n_full_tiles : 1;

    detector_kernel<<<blocks, TB>>>(box, conf, score4, prior, feat,
                                    box_out, probs, cls,
                                    n_boxes, prior_mod, n_full_tiles);
}

// round 7
// speedup vs baseline: 1.1411x; 1.0345x over previous
#include <cuda_runtime.h>
#include <cuda_bf16.h>
#include <cstdint>

// Detector post-process: persistent blocks, depth-2 TMA-bulk ring with 64-box
// tiles (TB=256), 4-threads-per-box packed-shuffle argmax.
//
// Output (flat float32): [box_out (B*4) | probs (B) | class_index (B)]

#ifndef THRESHOLD
#define THRESHOLD 0.5f
#endif

#define TB 256                    // threads per block
#define BOXES 64                  // boxes per tile
#define SC_BYTES (BOXES * 320)    // 20480 contiguous score bytes per tile
#define BX_OFF SC_BYTES           // box region offset (1024 B)
#define CF_OFF (SC_BYTES + 1024)  // conf region offset (256 B)
#define STAGE_BYTES (SC_BYTES + 1024 + 256)   // 21760
#define DEPTH 2

__device__ __forceinline__ uint32_t s2u32(const void* p) {
    return (uint32_t)__cvta_generic_to_shared(p);
}
__device__ __forceinline__ void mbar_init(uint32_t mb, uint32_t cnt) {
    asm volatile("mbarrier.init.shared.b64 [%0], %1;" :: "r"(mb), "r"(cnt) : "memory");
}
__device__ __forceinline__ void mbar_expect_tx(uint32_t mb, uint32_t bytes) {
    asm volatile("mbarrier.arrive.expect_tx.shared.b64 _, [%0], %1;"
                 :: "r"(mb), "r"(bytes) : "memory");
}
__device__ __forceinline__ void bulk_g2s(uint32_t sdst, const void* gsrc,
                                         uint32_t bytes, uint32_t mb) {
    asm volatile(
        "cp.async.bulk.shared::cta.global.mbarrier::complete_tx::bytes "
        "[%0], [%1], %2, [%3];"
        :: "r"(sdst), "l"(gsrc), "r"(bytes), "r"(mb) : "memory");
}
__device__ __forceinline__ void mbar_wait(uint32_t mb, uint32_t ph) {
    asm volatile(
        "{\n\t.reg .pred P;\n\t"
        "W%=:\n\t"
        "mbarrier.try_wait.parity.acquire.cta.shared::cta.b64 P, [%0], %1;\n\t"
        "@!P bra W%=;\n\t"
        "}"
        :: "r"(mb), "r"(ph) : "memory");
}

__global__ __launch_bounds__(TB) void detector_kernel(
    const float4* __restrict__ box,
    const float*  __restrict__ conf,
    const float4* __restrict__ score4,     // [B*20]
    const float4* __restrict__ prior,
    const unsigned* __restrict__ feat_raw,
    float4* __restrict__ box_out,
    float*  __restrict__ probs_out,
    float*  __restrict__ cls_out,
    int n_boxes, int prior_mod, int n_full_tiles)
{
    __shared__ __align__(128) char ring[DEPTH][STAGE_BYTES];  // 43520 B
    __shared__ unsigned long long mbar[DEPTH];

    const int t = threadIdx.x;

    if (t == 0) {
        #pragma unroll
        for (int d = 0; d < DEPTH; d++) mbar_init(s2u32(&mbar[d]), 1);
        asm volatile("fence.proxy.async.shared::cta;" ::: "memory");
    }
    __syncthreads();

    // feat_size may arrive as int32 or float32 bits; decode robustly.
    unsigned fb = *feat_raw;
    float feat = (fb < 0x01000000u) ? (float)fb : __uint_as_float(fb);
    float inv_feat = 1.0f / feat;

    auto prefetch = [&](int tile, int st) {
        if (t == 0 && tile < n_full_tiles) {
            uint32_t sb = s2u32(&ring[st][0]);
            uint32_t mb = s2u32(&mbar[st]);
            const char* sc_src = (const char*)score4 + (size_t)tile * SC_BYTES;
            mbar_expect_tx(mb, STAGE_BYTES);
            bulk_g2s(sb,          sc_src,              SC_BYTES, mb);
            bulk_g2s(sb + BX_OFF, box  + tile * BOXES, 1024,     mb);
            bulk_g2s(sb + CF_OFF, conf + tile * BOXES, 256,      mb);
        }
    };

    int tile = blockIdx.x;
    const int stride = gridDim.x;

    prefetch(tile, 0);

    const int bx = t >> 2;     // box within tile (0..63)
    const int q  = t & 3;      // quarter of the 80 classes

    int idx = 0;
    for (; tile < n_full_tiles; tile += stride, idx++) {
        const int bf = idx & 1;
        const int ph = (idx >> 1) & 1;

        prefetch(tile + stride, bf ^ 1);
        mbar_wait(s2u32(&mbar[bf]), ph);

        // ---- compute: 4 threads per box, 5 float4 slots each ----
        const int i = tile * BOXES + bx;
        {
            const float4* s = (const float4*)&ring[bf][0] + bx * 20 + q * 5;
            const float c = ((const float*)&ring[bf][CF_OFF])[bx];
            float best = -3.402823466e+38f;
            int bidx = 0;
            #pragma unroll
            for (int j = 0; j < 5; j++) {
                float4 v = s[j];
                float p0 = c * v.x, p1 = c * v.y, p2 = c * v.z, p3 = c * v.w;
                int base = (q * 5 + j) * 4;
                if (p0 > best) { best = p0; bidx = base;     }
                if (p1 > best) { best = p1; bidx = base + 1; }
                if (p2 > best) { best = p2; bidx = base + 2; }
                if (p3 > best) { best = p3; bidx = base + 3; }
            }
            // pack: non-negative fp32 bits monotonic; low byte favors smaller
            // class on exact ties (matches jnp.argmax first occurrence).
            unsigned long long pk =
                ((unsigned long long)__float_as_uint(best) << 32) |
                (unsigned)(127 - bidx);
            unsigned long long o1 = __shfl_xor_sync(0xFFFFFFFFu, pk, 1, 4);
            if (o1 > pk) pk = o1;
            unsigned long long o2 = __shfl_xor_sync(0xFFFFFFFFu, pk, 2, 4);
            if (o2 > pk) pk = o2;

            if (q == 0) {
                float prob = __uint_as_float((unsigned)(pk >> 32));
                int cls = 127 - (int)(pk & 0xFFu);

                float4 b4 = ((const float4*)&ring[bf][BX_OFF])[bx];
                float4 p  = prior[i % prior_mod];
                float cx = b4.x + p.x;
                float cy = b4.y + p.y;
                float hw = 0.5f * (b4.z * p.z);
                float hh = 0.5f * (b4.w * p.w);

                float4 corners;
                corners.x = (cx - hw) * inv_feat;
                corners.y = (cy - hh) * inv_feat;
                corners.z = (cx + hw) * inv_feat;
                corners.w = (cy + hh) * inv_feat;

                bool m = prob > THRESHOLD;
                box_out[i]   = m ? corners : make_float4(0.f, 0.f, 0.f, 0.f);
                probs_out[i] = m ? prob : 0.0f;
                cls_out[i]   = (float)cls;
            }
        }
        __syncthreads();   // all reads done before this stage is re-armed
    }

    // ---- tail boxes (n_boxes not multiple of BOXES): direct GMEM path ----
    int tail0 = n_full_tiles * BOXES;
    if (blockIdx.x == 0 && tail0 < n_boxes) {
        int i = tail0 + bx;
        if (i < n_boxes) {
            float c = conf[i];
            const float4* s = score4 + (size_t)i * 20 + q * 5;
            float best = -3.402823466e+38f;
            int bidx = 0;
            #pragma unroll
            for (int j = 0; j < 5; j++) {
                float4 v = s[j];
                float p0 = c * v.x, p1 = c * v.y, p2 = c * v.z, p3 = c * v.w;
                int base = (q * 5 + j) * 4;
                if (p0 > best) { best = p0; bidx = base;     }
                if (p1 > best) { best = p1; bidx = base + 1; }
                if (p2 > best) { best = p2; bidx = base + 2; }
                if (p3 > best) { best = p3; bidx = base + 3; }
            }
            unsigned long long pk =
                ((unsigned long long)__float_as_uint(best) << 32) |
                (unsigned)(127 - bidx);
            unsigned long long o1 = __shfl_xor_sync(0xFFFFFFFFu, pk, 1, 4);
            if (o1 > pk) pk = o1;
            unsigned long long o2 = __shfl_xor_sync(0xFFFFFFFFu, pk, 2, 4);
            if (o2 > pk) pk = o2;
            if (q == 0) {
                float prob = __uint_as_float((unsigned)(pk >> 32));
                int cls = 127 - (int)(pk & 0xFFu);
                float4 b4 = box[i];
                float4 p  = prior[i % prior_mod];
                float cx = b4.x + p.x, cy = b4.y + p.y;
                float hw = 0.5f * (b4.z * p.z), hh = 0.5f * (b4.w * p.w);
                float4 corners;
                corners.x = (cx - hw) * inv_feat;
                corners.y = (cy - hh) * inv_feat;
                corners.z = (cx + hw) * inv_feat;
                corners.w = (cy + hh) * inv_feat;
                bool m = prob > THRESHOLD;
                box_out[i]   = m ? corners : make_float4(0.f, 0.f, 0.f, 0.f);
                probs_out[i] = m ? prob : 0.0f;
                cls_out[i]   = (float)cls;
            }
        }
    }
}

extern "C" void kernel_launch(void* const* d_in, const int* in_sizes, int n_in,
                              void* d_out, int out_size)
{
    const float4*   box    = (const float4*)d_in[0];
    const float*    conf   = (const float*)d_in[1];
    const float4*   score4 = (const float4*)d_in[2];
    const float4*   prior  = (const float4*)d_in[3];
    const unsigned* feat   = (const unsigned*)d_in[4];

    int n_boxes      = in_sizes[1];       // N*HW*A
    int prior_mod    = in_sizes[3] / 4;   // HW*A
    int n_full_tiles = n_boxes / BOXES;

    float* out       = (float*)d_out;
    float4* box_out  = (float4*)out;
    float*  probs    = out + (size_t)n_boxes * 4;
    float*  cls      = out + (size_t)n_boxes * 5;

    int blocks = 148 * 5;                 // persistent, 5 blocks/SM (43.5 KB)
    if (blocks > n_full_tiles) blocks = n_full_tiles > 0 ? n_full_tiles : 1;

    detector_kernel<<<blocks, TB>>>(box, conf, score4, prior, feat,
                                    box_out, probs, cls,
                                    n_boxes, prior_mod, n_full_tiles);
}